// round 1
// baseline (speedup 1.0000x reference)
#include <cuda_runtime.h>
#include <cuda_bf16.h>
#include <math.h>

// ---------------- problem constants ----------------
#define BATCH 2
#define T 1024
#define VOCAB 50304
#define E 768
#define L 12
#define H 12
#define HS 64
#define F4 3072
#define ROWS (BATCH * T)   // 2048

// ---------------- scratch (device globals; no allocation allowed) -----------
__device__ float g_x  [ROWS * E];
__device__ float g_xn [ROWS * E];
__device__ float g_q  [ROWS * E];
__device__ float g_k  [ROWS * E];
__device__ float g_v  [ROWS * E];
__device__ float g_att[ROWS * E];
__device__ float g_h  [ROWS * F4];

// ---------------- embedding: x = tok_emb[idx] + pos_emb[t] ------------------
__global__ void embed_kernel(const int* __restrict__ idx,
                             const float* __restrict__ tok_emb,
                             const float* __restrict__ pos_emb,
                             float* __restrict__ x)
{
    int row = blockIdx.x;            // 0..ROWS-1
    int t   = row % T;
    int tok = idx[row];
    const float* te = tok_emb + (size_t)tok * E;
    const float* pe = pos_emb + (size_t)t * E;
    float* xr = x + (size_t)row * E;
    for (int i = threadIdx.x; i < E; i += blockDim.x)
        xr[i] = te[i] + pe[i];
}

// ---------------- layernorm (population variance, eps=1e-5) -----------------
__global__ __launch_bounds__(256)
void layernorm_kernel(const float* __restrict__ x,
                      const float* __restrict__ g,
                      const float* __restrict__ b,
                      float* __restrict__ y)
{
    int row = blockIdx.x;
    const float* xr = x + (size_t)row * E;
    float* yr = y + (size_t)row * E;
    int tid = threadIdx.x;

    float s = 0.f, s2 = 0.f;
    for (int i = tid; i < E; i += 256) {
        float v = xr[i];
        s += v; s2 += v * v;
    }
    // warp reduce
    #pragma unroll
    for (int o = 16; o > 0; o >>= 1) {
        s  += __shfl_down_sync(0xffffffffu, s,  o);
        s2 += __shfl_down_sync(0xffffffffu, s2, o);
    }
    __shared__ float ws[8], ws2[8];
    int wid = tid >> 5, lane = tid & 31;
    if (lane == 0) { ws[wid] = s; ws2[wid] = s2; }
    __syncthreads();
    if (tid == 0) {
        float a = 0.f, a2 = 0.f;
        #pragma unroll
        for (int i = 0; i < 8; i++) { a += ws[i]; a2 += ws2[i]; }
        ws[0] = a; ws2[0] = a2;
    }
    __syncthreads();
    float mean = ws[0] * (1.0f / E);
    float var  = ws2[0] * (1.0f / E) - mean * mean;
    float inv  = rsqrtf(var + 1e-5f);
    for (int i = tid; i < E; i += 256)
        yr[i] = (xr[i] - mean) * inv * g[i] + b[i];
}

// ---------------- SGEMM: C = A[M,K] @ W[K,N] (+bias)(+res)(relu) ------------
// 128x128 block tile, BK=8, 8x8 per thread, 256 threads. All dims assumed
// multiples of (128,128,8) — true for every GEMM in this model.
template<int DO_BIAS, int DO_RES, int DO_RELU>
__global__ __launch_bounds__(256)
void sgemm_kernel(const float* __restrict__ A,
                  const float* __restrict__ W,
                  const float* __restrict__ bias,
                  const float* __restrict__ res,
                  float* __restrict__ C,
                  int M, int N, int K)
{
    __shared__ float As[8][128];
    __shared__ float Bs[8][128];

    const int tid = threadIdx.x;
    const int tx = tid & 15;      // 0..15 (N dir)
    const int ty = tid >> 4;      // 0..15 (M dir)
    const int row0 = blockIdx.y * 128;
    const int col0 = blockIdx.x * 128;

    // A tile loader: 128 rows x 8 cols; one float4 per thread
    const int a_row = tid >> 1;
    const int a_col = (tid & 1) * 4;
    // B tile loader: 8 rows x 128 cols; one float4 per thread
    const int b_row = tid >> 5;
    const int b_col = (tid & 31) * 4;

    const float* Aptr = A + (size_t)(row0 + a_row) * K + a_col;
    const float* Wptr = W + (size_t)b_row * N + col0 + b_col;

    float acc[8][8];
    #pragma unroll
    for (int i = 0; i < 8; i++)
        #pragma unroll
        for (int j = 0; j < 8; j++) acc[i][j] = 0.f;

    for (int k0 = 0; k0 < K; k0 += 8) {
        float4 av = *reinterpret_cast<const float4*>(Aptr);
        As[a_col + 0][a_row] = av.x;
        As[a_col + 1][a_row] = av.y;
        As[a_col + 2][a_row] = av.z;
        As[a_col + 3][a_row] = av.w;
        *reinterpret_cast<float4*>(&Bs[b_row][b_col]) =
            *reinterpret_cast<const float4*>(Wptr);
        __syncthreads();

        #pragma unroll
        for (int k = 0; k < 8; k++) {
            float ra[8], rb[8];
            *reinterpret_cast<float4*>(&ra[0]) = *reinterpret_cast<const float4*>(&As[k][ty * 8]);
            *reinterpret_cast<float4*>(&ra[4]) = *reinterpret_cast<const float4*>(&As[k][ty * 8 + 4]);
            *reinterpret_cast<float4*>(&rb[0]) = *reinterpret_cast<const float4*>(&Bs[k][tx * 8]);
            *reinterpret_cast<float4*>(&rb[4]) = *reinterpret_cast<const float4*>(&Bs[k][tx * 8 + 4]);
            #pragma unroll
            for (int i = 0; i < 8; i++)
                #pragma unroll
                for (int j = 0; j < 8; j++)
                    acc[i][j] += ra[i] * rb[j];
        }
        __syncthreads();
        Aptr += 8;
        Wptr += (size_t)8 * N;
    }

    #pragma unroll
    for (int i = 0; i < 8; i++) {
        const size_t r = row0 + ty * 8 + i;
        #pragma unroll
        for (int j = 0; j < 8; j += 4) {
            const int c = col0 + tx * 8 + j;
            float4 v;
            v.x = acc[i][j + 0];
            v.y = acc[i][j + 1];
            v.z = acc[i][j + 2];
            v.w = acc[i][j + 3];
            if (DO_BIAS) {
                float4 bv = *reinterpret_cast<const float4*>(bias + c);
                v.x += bv.x; v.y += bv.y; v.z += bv.z; v.w += bv.w;
            }
            if (DO_RES) {
                float4 rv = *reinterpret_cast<const float4*>(res + r * N + c);
                v.x += rv.x; v.y += rv.y; v.z += rv.z; v.w += rv.w;
            }
            if (DO_RELU) {
                v.x = fmaxf(v.x, 0.f); v.y = fmaxf(v.y, 0.f);
                v.z = fmaxf(v.z, 0.f); v.w = fmaxf(v.w, 0.f);
            }
            *reinterpret_cast<float4*>(C + r * N + c) = v;
        }
    }
}

// ---------------- causal attention: one block per (b,h,query row) -----------
// q/k/v are [ROWS, E] with head h occupying columns [h*64, h*64+64).
__global__ __launch_bounds__(128)
void attention_kernel(const float* __restrict__ q,
                      const float* __restrict__ k,
                      const float* __restrict__ v,
                      float* __restrict__ att)
{
    const int qi = blockIdx.x % T;
    const int h  = (blockIdx.x / T) % H;
    const int b  = blockIdx.x / (T * H);
    const int tid = threadIdx.x;  // 128 threads

    __shared__ float sq[HS];
    __shared__ float sc[T];
    __shared__ float red[128];

    const float scale = rsqrtf((float)HS);
    const size_t rowq = (size_t)(b * T + qi);

    if (tid < HS) sq[tid] = q[rowq * E + h * HS + tid];
    __syncthreads();

    const float* kbase = k + (size_t)b * T * E + h * HS;

    // scores for assigned keys
    float lmax = -1e30f;
    for (int j = tid; j <= qi; j += 128) {
        const float4* kr = reinterpret_cast<const float4*>(kbase + (size_t)j * E);
        const float4* sq4 = reinterpret_cast<const float4*>(sq);
        float s = 0.f;
        #pragma unroll
        for (int d = 0; d < HS / 4; d++) {
            float4 kv = kr[d];
            float4 qv = sq4[d];
            s += qv.x * kv.x + qv.y * kv.y + qv.z * kv.z + qv.w * kv.w;
        }
        s *= scale;
        sc[j] = s;
        lmax = fmaxf(lmax, s);
    }
    red[tid] = lmax;
    __syncthreads();
    #pragma unroll
    for (int st = 64; st > 0; st >>= 1) {
        if (tid < st) red[tid] = fmaxf(red[tid], red[tid + st]);
        __syncthreads();
    }
    const float m = red[0];
    __syncthreads();

    float lsum = 0.f;
    for (int j = tid; j <= qi; j += 128) {
        float e = __expf(sc[j] - m);
        sc[j] = e;
        lsum += e;
    }
    red[tid] = lsum;
    __syncthreads();
    #pragma unroll
    for (int st = 64; st > 0; st >>= 1) {
        if (tid < st) red[tid] += red[tid + st];
        __syncthreads();
    }
    const float inv = 1.f / red[0];
    __syncthreads();

    // out[d] = sum_j p[j] * v[j][d]; threads: d = tid&63, half = tid>>6
    const int d = tid & 63;
    const int half = tid >> 6;
    const float* vb = v + (size_t)b * T * E + h * HS + d;
    float o = 0.f;
    for (int j = half; j <= qi; j += 2)
        o += sc[j] * vb[(size_t)j * E];
    red[tid] = o;
    __syncthreads();
    if (tid < HS)
        att[rowq * E + h * HS + tid] = (red[tid] + red[tid + 64]) * inv;
}

// ---------------- host orchestration ----------------------------------------
static inline void run_gemm(const float* A, const float* W, const float* bias,
                            const float* res, float* C, int M, int N, int K,
                            int do_bias, int do_res, int do_relu)
{
    dim3 grid(N / 128, M / 128);
    dim3 block(256);
    if (do_bias && do_res)
        sgemm_kernel<1, 1, 0><<<grid, block>>>(A, W, bias, res, C, M, N, K);
    else if (do_bias && do_relu)
        sgemm_kernel<1, 0, 1><<<grid, block>>>(A, W, bias, res, C, M, N, K);
    else if (do_bias)
        sgemm_kernel<1, 0, 0><<<grid, block>>>(A, W, bias, res, C, M, N, K);
    else
        sgemm_kernel<0, 0, 0><<<grid, block>>>(A, W, bias, res, C, M, N, K);
}

extern "C" void kernel_launch(void* const* d_in, const int* in_sizes, int n_in,
                              void* d_out, int out_size)
{
    const int*   idx     = (const int*)  d_in[0];
    const float* tok_emb = (const float*)d_in[1];
    const float* pos_emb = (const float*)d_in[2];
    const float* wq      = (const float*)d_in[3];
    const float* wk      = (const float*)d_in[4];
    const float* wv      = (const float*)d_in[5];
    const float* wproj   = (const float*)d_in[6];
    const float* bproj   = (const float*)d_in[7];
    const float* ln1_g   = (const float*)d_in[8];
    const float* ln1_b   = (const float*)d_in[9];
    const float* ln2_g   = (const float*)d_in[10];
    const float* ln2_b   = (const float*)d_in[11];
    const float* wfc     = (const float*)d_in[12];
    const float* bfc     = (const float*)d_in[13];
    const float* wpr2    = (const float*)d_in[14];
    const float* bpr2    = (const float*)d_in[15];
    const float* lnf_g   = (const float*)d_in[16];
    const float* lnf_b   = (const float*)d_in[17];
    const float* lm_w    = (const float*)d_in[18];
    const float* lm_b    = (const float*)d_in[19];
    float* out = (float*)d_out;

    float *x, *xn, *q, *k, *v, *att, *hbuf;
    cudaGetSymbolAddress((void**)&x,    g_x);
    cudaGetSymbolAddress((void**)&xn,   g_xn);
    cudaGetSymbolAddress((void**)&q,    g_q);
    cudaGetSymbolAddress((void**)&k,    g_k);
    cudaGetSymbolAddress((void**)&v,    g_v);
    cudaGetSymbolAddress((void**)&att,  g_att);
    cudaGetSymbolAddress((void**)&hbuf, g_h);

    embed_kernel<<<ROWS, 256>>>(idx, tok_emb, pos_emb, x);

    for (int l = 0; l < L; l++) {
        const float* wq_l    = wq    + (size_t)l * E * E;
        const float* wk_l    = wk    + (size_t)l * E * E;
        const float* wv_l    = wv    + (size_t)l * E * E;
        const float* wproj_l = wproj + (size_t)l * E * E;
        const float* bproj_l = bproj + (size_t)l * E;
        const float* g1 = ln1_g + (size_t)l * E;
        const float* b1 = ln1_b + (size_t)l * E;
        const float* g2 = ln2_g + (size_t)l * E;
        const float* b2 = ln2_b + (size_t)l * E;
        const float* wfc_l  = wfc  + (size_t)l * E * F4;
        const float* bfc_l  = bfc  + (size_t)l * F4;
        const float* wpr2_l = wpr2 + (size_t)l * F4 * E;
        const float* bpr2_l = bpr2 + (size_t)l * E;

        layernorm_kernel<<<ROWS, 256>>>(x, g1, b1, xn);
        run_gemm(xn, wq_l, nullptr, nullptr, q, ROWS, E, E, 0, 0, 0);
        run_gemm(xn, wk_l, nullptr, nullptr, k, ROWS, E, E, 0, 0, 0);
        run_gemm(xn, wv_l, nullptr, nullptr, v, ROWS, E, E, 0, 0, 0);
        attention_kernel<<<BATCH * H * T, 128>>>(q, k, v, att);
        // x = x + att @ wproj + bproj
        run_gemm(att, wproj_l, bproj_l, x, x, ROWS, E, E, 1, 1, 0);
        layernorm_kernel<<<ROWS, 256>>>(x, g2, b2, xn);
        // h = relu(xn @ wfc + bfc)
        run_gemm(xn, wfc_l, bfc_l, nullptr, hbuf, ROWS, F4, E, 1, 0, 1);
        // x = x + h @ wpr2 + bpr2
        run_gemm(hbuf, wpr2_l, bpr2_l, x, x, ROWS, E, F4, 1, 1, 0);
    }

    layernorm_kernel<<<ROWS, 256>>>(x, lnf_g, lnf_b, xn);
    // logits = xn @ lm_w + lm_b  -> directly into d_out
    run_gemm(xn, lm_w, lm_b, nullptr, out, ROWS, VOCAB, E, 1, 0, 0);
}

// round 2
// speedup vs baseline: 1.0459x; 1.0459x over previous
#include <cuda_runtime.h>
#include <cuda_bf16.h>
#include <math.h>

// ---------------- problem constants ----------------
#define BATCH 2
#define T 1024
#define VOCAB 50304
#define E 768
#define L 12
#define H 12
#define HS 64
#define F4 3072
#define ROWS (BATCH * T)   // 2048

// ---------------- scratch (device globals; no allocation allowed) -----------
__device__ float g_x  [ROWS * E];
__device__ float g_xn [ROWS * E];
__device__ float g_q  [ROWS * E];
__device__ float g_k  [ROWS * E];
__device__ float g_v  [ROWS * E];
__device__ float g_att[ROWS * E];
__device__ float g_h  [ROWS * F4];

// ---------------- embedding: x = tok_emb[idx] + pos_emb[t] ------------------
__global__ void embed_kernel(const int* __restrict__ idx,
                             const float* __restrict__ tok_emb,
                             const float* __restrict__ pos_emb,
                             float* __restrict__ x)
{
    int row = blockIdx.x;            // 0..ROWS-1
    int t   = row % T;
    int tok = idx[row];
    const float* te = tok_emb + (size_t)tok * E;
    const float* pe = pos_emb + (size_t)t * E;
    float* xr = x + (size_t)row * E;
    for (int i = threadIdx.x; i < E; i += blockDim.x)
        xr[i] = te[i] + pe[i];
}

// ---------------- layernorm (population variance, eps=1e-5) -----------------
__global__ __launch_bounds__(256)
void layernorm_kernel(const float* __restrict__ x,
                      const float* __restrict__ g,
                      const float* __restrict__ b,
                      float* __restrict__ y)
{
    int row = blockIdx.x;
    const float* xr = x + (size_t)row * E;
    float* yr = y + (size_t)row * E;
    int tid = threadIdx.x;

    float s = 0.f, s2 = 0.f;
    for (int i = tid; i < E; i += 256) {
        float v = xr[i];
        s += v; s2 += v * v;
    }
    // warp reduce
    #pragma unroll
    for (int o = 16; o > 0; o >>= 1) {
        s  += __shfl_down_sync(0xffffffffu, s,  o);
        s2 += __shfl_down_sync(0xffffffffu, s2, o);
    }
    __shared__ float ws[8], ws2[8];
    int wid = tid >> 5, lane = tid & 31;
    if (lane == 0) { ws[wid] = s; ws2[wid] = s2; }
    __syncthreads();
    if (tid == 0) {
        float a = 0.f, a2 = 0.f;
        #pragma unroll
        for (int i = 0; i < 8; i++) { a += ws[i]; a2 += ws2[i]; }
        ws[0] = a; ws2[0] = a2;
    }
    __syncthreads();
    float mean = ws[0] * (1.0f / E);
    float var  = ws2[0] * (1.0f / E) - mean * mean;
    float inv  = rsqrtf(var + 1e-5f);
    for (int i = tid; i < E; i += 256)
        yr[i] = (xr[i] - mean) * inv * g[i] + b[i];
}

// ---------------- SGEMM: C = A[M,K] @ W[K,N] (+bias)(+res)(relu) ------------
// 128x128 block tile, BK=8, 8x8 per thread, 256 threads. All dims assumed
// multiples of (128,128,8) — true for every GEMM in this model.
template<int DO_BIAS, int DO_RES, int DO_RELU>
__global__ __launch_bounds__(256)
void sgemm_kernel(const float* __restrict__ A,
                  const float* __restrict__ W,
                  const float* __restrict__ bias,
                  const float* __restrict__ res,
                  float* __restrict__ C,
                  int M, int N, int K)
{
    __shared__ float As[8][128];
    __shared__ float Bs[8][128];

    const int tid = threadIdx.x;
    const int tx = tid & 15;      // 0..15 (N dir)
    const int ty = tid >> 4;      // 0..15 (M dir)
    const int row0 = blockIdx.y * 128;
    const int col0 = blockIdx.x * 128;

    // A tile loader: 128 rows x 8 cols; one float4 per thread
    const int a_row = tid >> 1;
    const int a_col = (tid & 1) * 4;
    // B tile loader: 8 rows x 128 cols; one float4 per thread
    const int b_row = tid >> 5;
    const int b_col = (tid & 31) * 4;

    const float* Aptr = A + (size_t)(row0 + a_row) * K + a_col;
    const float* Wptr = W + (size_t)b_row * N + col0 + b_col;

    float acc[8][8];
    #pragma unroll
    for (int i = 0; i < 8; i++)
        #pragma unroll
        for (int j = 0; j < 8; j++) acc[i][j] = 0.f;

    for (int k0 = 0; k0 < K; k0 += 8) {
        float4 av = *reinterpret_cast<const float4*>(Aptr);
        As[a_col + 0][a_row] = av.x;
        As[a_col + 1][a_row] = av.y;
        As[a_col + 2][a_row] = av.z;
        As[a_col + 3][a_row] = av.w;
        *reinterpret_cast<float4*>(&Bs[b_row][b_col]) =
            *reinterpret_cast<const float4*>(Wptr);
        __syncthreads();

        #pragma unroll
        for (int k = 0; k < 8; k++) {
            float ra[8], rb[8];
            *reinterpret_cast<float4*>(&ra[0]) = *reinterpret_cast<const float4*>(&As[k][ty * 8]);
            *reinterpret_cast<float4*>(&ra[4]) = *reinterpret_cast<const float4*>(&As[k][ty * 8 + 4]);
            *reinterpret_cast<float4*>(&rb[0]) = *reinterpret_cast<const float4*>(&Bs[k][tx * 8]);
            *reinterpret_cast<float4*>(&rb[4]) = *reinterpret_cast<const float4*>(&Bs[k][tx * 8 + 4]);
            #pragma unroll
            for (int i = 0; i < 8; i++)
                #pragma unroll
                for (int j = 0; j < 8; j++)
                    acc[i][j] += ra[i] * rb[j];
        }
        __syncthreads();
        Aptr += 8;
        Wptr += (size_t)8 * N;
    }

    #pragma unroll
    for (int i = 0; i < 8; i++) {
        const size_t r = row0 + ty * 8 + i;
        #pragma unroll
        for (int j = 0; j < 8; j += 4) {
            const int c = col0 + tx * 8 + j;
            float4 v;
            v.x = acc[i][j + 0];
            v.y = acc[i][j + 1];
            v.z = acc[i][j + 2];
            v.w = acc[i][j + 3];
            if (DO_BIAS) {
                float4 bv = *reinterpret_cast<const float4*>(bias + c);
                v.x += bv.x; v.y += bv.y; v.z += bv.z; v.w += bv.w;
            }
            if (DO_RES) {
                float4 rv = *reinterpret_cast<const float4*>(res + r * N + c);
                v.x += rv.x; v.y += rv.y; v.z += rv.z; v.w += rv.w;
            }
            if (DO_RELU) {
                v.x = fmaxf(v.x, 0.f); v.y = fmaxf(v.y, 0.f);
                v.z = fmaxf(v.z, 0.f); v.w = fmaxf(v.w, 0.f);
            }
            *reinterpret_cast<float4*>(C + r * N + c) = v;
        }
    }
}

// ---------------- causal attention: one block per (b,h,query row) -----------
// q/k/v are [ROWS, E] with head h occupying columns [h*64, h*64+64).
__global__ __launch_bounds__(128)
void attention_kernel(const float* __restrict__ q,
                      const float* __restrict__ k,
                      const float* __restrict__ v,
                      float* __restrict__ att)
{
    const int qi = blockIdx.x % T;
    const int h  = (blockIdx.x / T) % H;
    const int b  = blockIdx.x / (T * H);
    const int tid = threadIdx.x;  // 128 threads

    __shared__ float sq[HS];
    __shared__ float sc[T];
    __shared__ float red[128];

    const float scale = rsqrtf((float)HS);
    const size_t rowq = (size_t)(b * T + qi);

    if (tid < HS) sq[tid] = q[rowq * E + h * HS + tid];
    __syncthreads();

    const float* kbase = k + (size_t)b * T * E + h * HS;

    // scores for assigned keys
    float lmax = -1e30f;
    for (int j = tid; j <= qi; j += 128) {
        const float4* kr = reinterpret_cast<const float4*>(kbase + (size_t)j * E);
        const float4* sq4 = reinterpret_cast<const float4*>(sq);
        float s = 0.f;
        #pragma unroll
        for (int d = 0; d < HS / 4; d++) {
            float4 kv = kr[d];
            float4 qv = sq4[d];
            s += qv.x * kv.x + qv.y * kv.y + qv.z * kv.z + qv.w * kv.w;
        }
        s *= scale;
        sc[j] = s;
        lmax = fmaxf(lmax, s);
    }
    red[tid] = lmax;
    __syncthreads();
    #pragma unroll
    for (int st = 64; st > 0; st >>= 1) {
        if (tid < st) red[tid] = fmaxf(red[tid], red[tid + st]);
        __syncthreads();
    }
    const float m = red[0];
    __syncthreads();

    float lsum = 0.f;
    for (int j = tid; j <= qi; j += 128) {
        float e = __expf(sc[j] - m);
        sc[j] = e;
        lsum += e;
    }
    red[tid] = lsum;
    __syncthreads();
    #pragma unroll
    for (int st = 64; st > 0; st >>= 1) {
        if (tid < st) red[tid] += red[tid + st];
        __syncthreads();
    }
    const float inv = 1.f / red[0];
    __syncthreads();

    // out[d] = sum_j p[j] * v[j][d]; threads: d = tid&63, half = tid>>6
    const int d = tid & 63;
    const int half = tid >> 6;
    const float* vb = v + (size_t)b * T * E + h * HS + d;
    float o = 0.f;
    for (int j = half; j <= qi; j += 2)
        o += sc[j] * vb[(size_t)j * E];
    red[tid] = o;
    __syncthreads();
    if (tid < HS)
        att[rowq * E + h * HS + tid] = (red[tid] + red[tid + 64]) * inv;
}

// ---------------- host orchestration ----------------------------------------
static inline void run_gemm(const float* A, const float* W, const float* bias,
                            const float* res, float* C, int M, int N, int K,
                            int do_bias, int do_res, int do_relu)
{
    dim3 grid(N / 128, M / 128);
    dim3 block(256);
    if (do_bias && do_res)
        sgemm_kernel<1, 1, 0><<<grid, block>>>(A, W, bias, res, C, M, N, K);
    else if (do_bias && do_relu)
        sgemm_kernel<1, 0, 1><<<grid, block>>>(A, W, bias, res, C, M, N, K);
    else if (do_bias)
        sgemm_kernel<1, 0, 0><<<grid, block>>>(A, W, bias, res, C, M, N, K);
    else
        sgemm_kernel<0, 0, 0><<<grid, block>>>(A, W, bias, res, C, M, N, K);
}

extern "C" void kernel_launch(void* const* d_in, const int* in_sizes, int n_in,
                              void* d_out, int out_size)
{
    const int*   idx     = (const int*)  d_in[0];
    const float* tok_emb = (const float*)d_in[1];
    const float* pos_emb = (const float*)d_in[2];
    const float* wq      = (const float*)d_in[3];
    const float* wk      = (const float*)d_in[4];
    const float* wv      = (const float*)d_in[5];
    const float* wproj   = (const float*)d_in[6];
    const float* bproj   = (const float*)d_in[7];
    const float* ln1_g   = (const float*)d_in[8];
    const float* ln1_b   = (const float*)d_in[9];
    const float* ln2_g   = (const float*)d_in[10];
    const float* ln2_b   = (const float*)d_in[11];
    const float* wfc     = (const float*)d_in[12];
    const float* bfc     = (const float*)d_in[13];
    const float* wpr2    = (const float*)d_in[14];
    const float* bpr2    = (const float*)d_in[15];
    const float* lnf_g   = (const float*)d_in[16];
    const float* lnf_b   = (const float*)d_in[17];
    const float* lm_w    = (const float*)d_in[18];
    const float* lm_b    = (const float*)d_in[19];
    float* out = (float*)d_out;

    float *x, *xn, *q, *k, *v, *att, *hbuf;
    cudaGetSymbolAddress((void**)&x,    g_x);
    cudaGetSymbolAddress((void**)&xn,   g_xn);
    cudaGetSymbolAddress((void**)&q,    g_q);
    cudaGetSymbolAddress((void**)&k,    g_k);
    cudaGetSymbolAddress((void**)&v,    g_v);
    cudaGetSymbolAddress((void**)&att,  g_att);
    cudaGetSymbolAddress((void**)&hbuf, g_h);

    embed_kernel<<<ROWS, 256>>>(idx, tok_emb, pos_emb, x);

    for (int l = 0; l < L; l++) {
        const float* wq_l    = wq    + (size_t)l * E * E;
        const float* wk_l    = wk    + (size_t)l * E * E;
        const float* wv_l    = wv    + (size_t)l * E * E;
        const float* wproj_l = wproj + (size_t)l * E * E;
        const float* bproj_l = bproj + (size_t)l * E;
        const float* g1 = ln1_g + (size_t)l * E;
        const float* b1 = ln1_b + (size_t)l * E;
        const float* g2 = ln2_g + (size_t)l * E;
        const float* b2 = ln2_b + (size_t)l * E;
        const float* wfc_l  = wfc  + (size_t)l * E * F4;
        const float* bfc_l  = bfc  + (size_t)l * F4;
        const float* wpr2_l = wpr2 + (size_t)l * F4 * E;
        const float* bpr2_l = bpr2 + (size_t)l * E;

        layernorm_kernel<<<ROWS, 256>>>(x, g1, b1, xn);
        run_gemm(xn, wq_l, nullptr, nullptr, q, ROWS, E, E, 0, 0, 0);
        run_gemm(xn, wk_l, nullptr, nullptr, k, ROWS, E, E, 0, 0, 0);
        run_gemm(xn, wv_l, nullptr, nullptr, v, ROWS, E, E, 0, 0, 0);
        attention_kernel<<<BATCH * H * T, 128>>>(q, k, v, att);
        // x = x + att @ wproj + bproj
        run_gemm(att, wproj_l, bproj_l, x, x, ROWS, E, E, 1, 1, 0);
        layernorm_kernel<<<ROWS, 256>>>(x, g2, b2, xn);
        // h = relu(xn @ wfc + bfc)
        run_gemm(xn, wfc_l, bfc_l, nullptr, hbuf, ROWS, F4, E, 1, 0, 1);
        // x = x + h @ wpr2 + bpr2
        run_gemm(hbuf, wpr2_l, bpr2_l, x, x, ROWS, E, F4, 1, 1, 0);
    }

    layernorm_kernel<<<ROWS, 256>>>(x, lnf_g, lnf_b, xn);
    // logits = xn @ lm_w + lm_b  -> directly into d_out
    run_gemm(xn, lm_w, lm_b, nullptr, out, ROWS, VOCAB, E, 1, 0, 0);
}

// round 4
// speedup vs baseline: 3.1530x; 3.0147x over previous
#include <cuda_runtime.h>
#include <cuda_bf16.h>
#include <math.h>

#define BATCH 2
#define T 1024
#define VOCAB 50304
#define E 768
#define L 12
#define H 12
#define HS 64
#define F4 3072
#define ROWS (BATCH * T)
#define BH (BATCH * H)

// ---------------- scratch ----------------
__device__ __align__(128) float          g_x   [ROWS * E];
__device__ __align__(128) __nv_bfloat16  g_xn3 [ROWS * 3 * E];
__device__ __align__(128) float          g_qkv [ROWS * 3 * E];
__device__ __align__(128) __nv_bfloat16  g_q3  [ROWS * 3 * E];
__device__ __align__(128) __nv_bfloat16  g_k3t [BH * 3 * HS * T];
__device__ __align__(128) __nv_bfloat16  g_v3  [BH * 3 * T * HS];
__device__ __align__(128) float          g_S   [(size_t)BH * T * T];
__device__ __align__(128) __nv_bfloat16  g_P3  [(size_t)BH * T * 3 * T];
__device__ __align__(128) __nv_bfloat16  g_att3[ROWS * 3 * E];
__device__ __align__(128) __nv_bfloat16  g_h3  [ROWS * 3 * F4];
__device__ __align__(128) __nv_bfloat16  g_w3  [3 * E * F4];
__device__ __align__(128) __nv_bfloat16  g_lm3 [(size_t)3 * E * VOCAB];

__device__ __forceinline__ unsigned smem_u32(const void* p) {
    unsigned a;
    asm("{ .reg .u64 t; cvta.to.shared.u64 t, %1; cvt.u32.u64 %0, t; }" : "=r"(a) : "l"(p));
    return a;
}
__device__ __forceinline__ void bsplit(float v, __nv_bfloat16& hi, __nv_bfloat16& lo) {
    hi = __float2bfloat16(v);
    lo = __float2bfloat16(v - __bfloat162float(hi));
}

// ---------------- bf16 mma.sync GEMM ----------------
// C[M,N](fp32 or triple-bf16) = A[M,K3] @ B[K3,N], K3 = 3K interleaved-64 split.
// mode 0: plain. mode 2: attention scores (z=b*H+h). mode 3: P @ V.
template<int BN, bool TOUT>
__global__ void __launch_bounds__(256)
hgemm(const __nv_bfloat16* __restrict__ A, const __nv_bfloat16* __restrict__ Bm,
      const float* __restrict__ bias, const float* __restrict__ res,
      float* __restrict__ Cf, __nv_bfloat16* __restrict__ C3,
      int lda, int ldb, int ldc, int K3, int mode, int relu)
{
    constexpr int CHB   = BN / 8;          // 16B chunks per B row
    constexpr int CNTB  = (64 * CHB) / 256;
    constexpr int AELEM = 128 * 64;        // elements per A stage
    constexpr int BELEM = 64 * BN;
    constexpr int WARPN = BN / 4;
    constexpr int NF    = WARPN / 8;

    const int m0 = blockIdx.x * 128, n0 = blockIdx.y * BN, z = blockIdx.z;
    if (mode == 2 && n0 > m0 + 127) return;

    extern __shared__ __nv_bfloat16 sm[];
    const unsigned Asb = smem_u32(sm);
    const unsigned Bsb = Asb + 3 * AELEM * 2;

    size_t rowb; int colb;
    const __nv_bfloat16 *Ag, *Bg;
    if (mode == 2) {
        int b = z / H, h = z - b * H;
        Ag = A + (size_t)(b * T + m0) * lda + h * 192;
        Bg = Bm + (size_t)z * 192 * ldb + n0;
        rowb = (size_t)z * T + m0; colb = n0;
    } else if (mode == 3) {
        int b = z / H, h = z - b * H;
        Ag = A + (size_t)(z * T + m0) * lda;
        Bg = Bm + (size_t)z * 3 * T * ldb + n0;
        rowb = (size_t)(b * T + m0); colb = h * 64 + n0;
    } else {
        Ag = A + (size_t)m0 * lda;
        Bg = Bm + n0;
        rowb = m0; colb = n0;
    }

    int kt = K3 / 64;
    if (mode == 3) { int c = 3 * (m0 / 64 + 2); if (c < kt) kt = c; }

    const int tid = threadIdx.x;
    const int w = tid >> 5, l = tid & 31;
    const int wm = w >> 2, wn = w & 3;

    auto loadStage = [&](int tt, int s) {
        const __nv_bfloat16* ag = Ag + tt * 64;
        #pragma unroll
        for (int i = 0; i < 4; i++) {
            int id = tid * 4 + i;
            int r = id >> 3, c = id & 7;
            unsigned dst = Asb + s * AELEM * 2 + r * 128 + ((c ^ (r & 7)) << 4);
            const __nv_bfloat16* src = ag + (size_t)r * lda + c * 8;
            asm volatile("cp.async.cg.shared.global [%0], [%1], 16;" :: "r"(dst), "l"(src));
        }
        const __nv_bfloat16* bg = Bg + (size_t)tt * 64 * ldb;
        #pragma unroll
        for (int i = 0; i < CNTB; i++) {
            int id = tid * CNTB + i;
            int r = id / CHB, c = id % CHB;
            unsigned dst = Bsb + s * BELEM * 2 + r * (BN * 2) + ((c ^ (r & 7)) << 4);
            const __nv_bfloat16* src = bg + (size_t)r * ldb + c * 8;
            asm volatile("cp.async.cg.shared.global [%0], [%1], 16;" :: "r"(dst), "l"(src));
        }
    };

    #pragma unroll
    for (int s = 0; s < 2; s++) {
        if (s < kt) loadStage(s, s);
        asm volatile("cp.async.commit_group;");
    }

    float acc[4][NF][4] = {};

    for (int t = 0; t < kt; t++) {
        if (t + 2 < kt) loadStage(t + 2, (t + 2) % 3);
        asm volatile("cp.async.commit_group;");
        asm volatile("cp.async.wait_group 2;");
        __syncthreads();
        unsigned as = Asb + (t % 3) * AELEM * 2;
        unsigned bs = Bsb + (t % 3) * BELEM * 2;
        #pragma unroll
        for (int kk = 0; kk < 4; kk++) {
            unsigned a[4][4], b[NF][2];
            #pragma unroll
            for (int i = 0; i < 4; i++) {
                int row = wm * 64 + i * 16 + (l & 15);
                int ch  = kk * 2 + (l >> 4);
                unsigned ad = as + row * 128 + ((ch ^ (row & 7)) << 4);
                asm volatile("ldmatrix.sync.aligned.m8n8.x4.shared.b16 {%0,%1,%2,%3}, [%4];"
                    : "=r"(a[i][0]), "=r"(a[i][1]), "=r"(a[i][2]), "=r"(a[i][3]) : "r"(ad));
            }
            #pragma unroll
            for (int p = 0; p < NF / 2; p++) {
                int row = kk * 16 + (l & 15);
                int ch  = wn * (WARPN / 8) + p * 2 + (l >> 4);
                unsigned bd = bs + row * (BN * 2) + ((ch ^ (row & 7)) << 4);
                unsigned r0, r1, r2, r3;
                asm volatile("ldmatrix.sync.aligned.m8n8.x4.trans.shared.b16 {%0,%1,%2,%3}, [%4];"
                    : "=r"(r0), "=r"(r1), "=r"(r2), "=r"(r3) : "r"(bd));
                b[2*p][0] = r0; b[2*p][1] = r1; b[2*p+1][0] = r2; b[2*p+1][1] = r3;
            }
            #pragma unroll
            for (int i = 0; i < 4; i++)
                #pragma unroll
                for (int j = 0; j < NF; j++)
                    asm volatile(
                        "mma.sync.aligned.m16n8k16.row.col.f32.bf16.bf16.f32 "
                        "{%0,%1,%2,%3}, {%4,%5,%6,%7}, {%8,%9}, {%0,%1,%2,%3};"
                        : "+f"(acc[i][j][0]), "+f"(acc[i][j][1]),
                          "+f"(acc[i][j][2]), "+f"(acc[i][j][3])
                        : "r"(a[i][0]), "r"(a[i][1]), "r"(a[i][2]), "r"(a[i][3]),
                          "r"(b[j][0]), "r"(b[j][1]));
        }
        __syncthreads();
    }

    // epilogue
    #pragma unroll
    for (int i = 0; i < 4; i++) {
        #pragma unroll
        for (int j = 0; j < NF; j++) {
            #pragma unroll
            for (int half = 0; half < 2; half++) {
                int rr = wm * 64 + i * 16 + (l >> 2) + half * 8;
                int c  = wn * WARPN + j * 8 + (l & 3) * 2;
                int cg = colb + c;
                float v0 = acc[i][j][half * 2 + 0];
                float v1 = acc[i][j][half * 2 + 1];
                size_t ro = rowb + rr;
                if (bias) { v0 += bias[cg]; v1 += bias[cg + 1]; }
                if (res)  { v0 += res[ro * ldc + cg]; v1 += res[ro * ldc + cg + 1]; }
                if (relu) { v0 = fmaxf(v0, 0.f); v1 = fmaxf(v1, 0.f); }
                if (TOUT) {
                    int kb = cg >> 6, kr = cg & 63;
                    size_t base = ro * ldc + 192 * kb + kr;
                    __nv_bfloat16 h0, l0, h1, l1;
                    bsplit(v0, h0, l0); bsplit(v1, h1, l1);
                    C3[base]       = h0; C3[base + 1]   = h1;
                    C3[base + 64]  = l0; C3[base + 65]  = l1;
                    C3[base + 128] = h0; C3[base + 129] = h1;
                } else {
                    Cf[ro * ldc + cg]     = v0;
                    Cf[ro * ldc + cg + 1] = v1;
                }
            }
        }
    }
}

// ---------------- small kernels ----------------
__global__ void embed_kernel(const int* __restrict__ idx, const float* __restrict__ te,
                             const float* __restrict__ pe, float* __restrict__ x)
{
    int row = blockIdx.x, t = row % T, tok = idx[row];
    const float* a = te + (size_t)tok * E;
    const float* b = pe + (size_t)t * E;
    float* xr = x + (size_t)row * E;
    for (int i = threadIdx.x; i < E; i += blockDim.x) xr[i] = a[i] + b[i];
}

__global__ __launch_bounds__(256)
void layernorm_kernel(const float* __restrict__ x, const float* __restrict__ g,
                      const float* __restrict__ b, __nv_bfloat16* __restrict__ y3)
{
    int row = blockIdx.x, tid = threadIdx.x;
    const float* xr = x + (size_t)row * E;
    float s = 0.f, s2 = 0.f;
    for (int i = tid; i < E; i += 256) { float v = xr[i]; s += v; s2 += v * v; }
    #pragma unroll
    for (int o = 16; o > 0; o >>= 1) {
        s += __shfl_down_sync(~0u, s, o); s2 += __shfl_down_sync(~0u, s2, o);
    }
    __shared__ float ws[8], ws2[8];
    if ((tid & 31) == 0) { ws[tid >> 5] = s; ws2[tid >> 5] = s2; }
    __syncthreads();
    if (tid == 0) {
        float a = 0.f, a2 = 0.f;
        #pragma unroll
        for (int i = 0; i < 8; i++) { a += ws[i]; a2 += ws2[i]; }
        ws[0] = a; ws2[0] = a2;
    }
    __syncthreads();
    float mean = ws[0] / E, var = ws2[0] / E - mean * mean;
    float inv = rsqrtf(var + 1e-5f);
    for (int i = tid; i < E; i += 256) {
        float v = (xr[i] - mean) * inv * g[i] + b[i];
        __nv_bfloat16 hi, lo; bsplit(v, hi, lo);
        size_t base = (size_t)row * (3 * E) + 192 * (i >> 6) + (i & 63);
        y3[base] = hi; y3[base + 64] = lo; y3[base + 128] = hi;
    }
}

// fp32 W[K,N] -> bf16 W3[3K,N] interleaved (B-side: hi,hi,lo)
__global__ void wsplit_kernel(const float* __restrict__ src, __nv_bfloat16* __restrict__ dst,
                              int N, int dstLD, int colOff)
{
    size_t i = (size_t)blockIdx.x * 256 + threadIdx.x;
    int n = (int)(i % N), k = (int)(i / N);
    float v = src[i];
    __nv_bfloat16 hi, lo; bsplit(v, hi, lo);
    size_t rb = (size_t)(192 * (k >> 6) + (k & 63)) * dstLD + colOff + n;
    dst[rb] = hi; dst[rb + (size_t)64 * dstLD] = hi; dst[rb + (size_t)128 * dstLD] = lo;
}

// q cols of qkv -> q3 (A-side: hi,lo,hi)
__global__ void qpack_kernel(const float* __restrict__ qkv, __nv_bfloat16* __restrict__ q3)
{
    size_t i = (size_t)blockIdx.x * 256 + threadIdx.x;  // over ROWS*E
    int c = (int)(i % E); size_t row = i / E;
    float v = qkv[row * (3 * E) + c];
    __nv_bfloat16 hi, lo; bsplit(v, hi, lo);
    size_t base = row * (3 * E) + (c >> 6) * 192 + (c & 63);
    q3[base] = hi; q3[base + 64] = lo; q3[base + 128] = hi;
}

// k cols -> k3t [z][192][T] transposed (B-side: hi,hi,lo)
__global__ void kpackT_kernel(const float* __restrict__ qkv, __nv_bfloat16* __restrict__ k3t)
{
    __shared__ float tile[32][33];
    int z = blockIdx.z, b = z / H, h = z - b * H;
    int t0 = blockIdx.x * 32, d0 = blockIdx.y * 32;
    int tx = threadIdx.x, ty = threadIdx.y;
    for (int i = ty; i < 32; i += 8)
        tile[i][tx] = qkv[(size_t)(b * T + t0 + i) * (3 * E) + E + h * 64 + d0 + tx];
    __syncthreads();
    for (int i = ty; i < 32; i += 8) {
        float v = tile[tx][i];
        __nv_bfloat16 hi, lo; bsplit(v, hi, lo);
        size_t rb = ((size_t)z * 192 + d0 + i) * T + t0 + tx;
        k3t[rb] = hi; k3t[rb + (size_t)64 * T] = hi; k3t[rb + (size_t)128 * T] = lo;
    }
}

// v cols -> v3 [z][3T][64] (B-side rows over K=T: hi,hi,lo)
__global__ void vpack_kernel(const float* __restrict__ qkv, __nv_bfloat16* __restrict__ v3)
{
    int z = blockIdx.y, b = z / H, h = z - b * H;
    int t = blockIdx.x * 4 + threadIdx.y;
    int d = threadIdx.x;
    float v = qkv[(size_t)(b * T + t) * (3 * E) + 2 * E + h * 64 + d];
    __nv_bfloat16 hi, lo; bsplit(v, hi, lo);
    size_t rb = ((size_t)z * 3 * T + 192 * (t >> 6) + (t & 63)) * 64 + d;
    v3[rb] = hi; v3[rb + 64 * 64] = hi; v3[rb + 128 * 64] = lo;
}

__global__ __launch_bounds__(128)
void softmax_kernel(const float* __restrict__ S, __nv_bfloat16* __restrict__ P3)
{
    int bid = blockIdx.x, z = bid >> 10, qi = bid & 1023, tid = threadIdx.x;
    const float* srow = S + ((size_t)z << 20) + ((size_t)qi << 10);
    __nv_bfloat16* prow = P3 + ((size_t)(z << 10) + qi) * (3 * T);
    __shared__ float sc[T];
    __shared__ float red[128];
    float lmax = -1e30f;
    for (int j = tid; j <= qi; j += 128) {
        float e = srow[j] * 0.125f;
        sc[j] = e; lmax = fmaxf(lmax, e);
    }
    red[tid] = lmax; __syncthreads();
    #pragma unroll
    for (int st = 64; st > 0; st >>= 1) {
        if (tid < st) red[tid] = fmaxf(red[tid], red[tid + st]);
        __syncthreads();
    }
    float m = red[0]; __syncthreads();
    float lsum = 0.f;
    for (int j = tid; j <= qi; j += 128) { float e = __expf(sc[j] - m); sc[j] = e; lsum += e; }
    red[tid] = lsum; __syncthreads();
    #pragma unroll
    for (int st = 64; st > 0; st >>= 1) {
        if (tid < st) red[tid] += red[tid + st];
        __syncthreads();
    }
    float inv = 1.f / red[0]; __syncthreads();
    for (int j = tid; j < 3 * T; j += 128) {
        int kb = j / 192, rr = j - kb * 192;
        int k = kb * 64 + (rr & 63);
        float p = (k <= qi) ? sc[k] * inv : 0.f;
        __nv_bfloat16 o;
        if ((rr >> 6) == 1) {
            __nv_bfloat16 hi = __float2bfloat16(p);
            o = __float2bfloat16(p - __bfloat162float(hi));
        } else o = __float2bfloat16(p);
        prow[j] = o;
    }
}

// ---------------- host ----------------
#define SMEM128 (3 * (128 * 64 + 64 * 128) * 2)
#define SMEM64  (3 * (128 * 64 + 64 * 64) * 2)

extern "C" void kernel_launch(void* const* d_in, const int* in_sizes, int n_in,
                              void* d_out, int out_size)
{
    const int*   idx     = (const int*)  d_in[0];
    const float* tok_emb = (const float*)d_in[1];
    const float* pos_emb = (const float*)d_in[2];
    const float* wq      = (const float*)d_in[3];
    const float* wk      = (const float*)d_in[4];
    const float* wv      = (const float*)d_in[5];
    const float* wproj   = (const float*)d_in[6];
    const float* bproj   = (const float*)d_in[7];
    const float* ln1_g   = (const float*)d_in[8];
    const float* ln1_b   = (const float*)d_in[9];
    const float* ln2_g   = (const float*)d_in[10];
    const float* ln2_b   = (const float*)d_in[11];
    const float* wfc     = (const float*)d_in[12];
    const float* bfc     = (const float*)d_in[13];
    const float* wpr2    = (const float*)d_in[14];
    const float* bpr2    = (const float*)d_in[15];
    const float* lnf_g   = (const float*)d_in[16];
    const float* lnf_b   = (const float*)d_in[17];
    const float* lm_w    = (const float*)d_in[18];
    const float* lm_b    = (const float*)d_in[19];
    float* out = (float*)d_out;

    cudaFuncSetAttribute(hgemm<128, false>, cudaFuncAttributeMaxDynamicSharedMemorySize, SMEM128);
    cudaFuncSetAttribute(hgemm<128, true>,  cudaFuncAttributeMaxDynamicSharedMemorySize, SMEM128);
    cudaFuncSetAttribute(hgemm<64,  true>,  cudaFuncAttributeMaxDynamicSharedMemorySize, SMEM64);

    float *x, *qkv, *S;
    __nv_bfloat16 *xn3, *q3, *k3t, *v3, *P3, *att3, *h3, *w3, *lm3;
    cudaGetSymbolAddress((void**)&x, g_x);     cudaGetSymbolAddress((void**)&xn3, g_xn3);
    cudaGetSymbolAddress((void**)&qkv, g_qkv); cudaGetSymbolAddress((void**)&q3, g_q3);
    cudaGetSymbolAddress((void**)&k3t, g_k3t); cudaGetSymbolAddress((void**)&v3, g_v3);
    cudaGetSymbolAddress((void**)&S, g_S);     cudaGetSymbolAddress((void**)&P3, g_P3);
    cudaGetSymbolAddress((void**)&att3, g_att3); cudaGetSymbolAddress((void**)&h3, g_h3);
    cudaGetSymbolAddress((void**)&w3, g_w3);   cudaGetSymbolAddress((void**)&lm3, g_lm3);

    dim3 tb(32, 8);
    embed_kernel<<<ROWS, 256>>>(idx, tok_emb, pos_emb, x);

    for (int l = 0; l < L; l++) {
        const float* wq_l  = wq  + (size_t)l * E * E;
        const float* wk_l  = wk  + (size_t)l * E * E;
        const float* wv_l  = wv  + (size_t)l * E * E;
        const float* wp_l  = wproj + (size_t)l * E * E;
        const float* wfc_l = wfc + (size_t)l * E * F4;
        const float* wp2_l = wpr2 + (size_t)l * F4 * E;

        layernorm_kernel<<<ROWS, 256>>>(x, ln1_g + l * E, ln1_b + l * E, xn3);

        wsplit_kernel<<<E * E / 256, 256>>>(wq_l, w3, E, 3 * E, 0);
        wsplit_kernel<<<E * E / 256, 256>>>(wk_l, w3, E, 3 * E, E);
        wsplit_kernel<<<E * E / 256, 256>>>(wv_l, w3, E, 3 * E, 2 * E);
        hgemm<128, false><<<dim3(16, 18, 1), 256, SMEM128>>>(
            xn3, w3, nullptr, nullptr, qkv, nullptr, 3 * E, 3 * E, 3 * E, 3 * E, 0, 0);

        qpack_kernel<<<ROWS * E / 256, 256>>>(qkv, q3);
        kpackT_kernel<<<dim3(32, 2, BH), tb>>>(qkv, k3t);
        vpack_kernel<<<dim3(T / 4, BH), dim3(64, 4)>>>(qkv, v3);

        hgemm<128, false><<<dim3(8, 8, BH), 256, SMEM128>>>(
            q3, k3t, nullptr, nullptr, S, nullptr, 3 * E, T, T, 192, 2, 0);
        softmax_kernel<<<BH * T, 128>>>(S, P3);
        hgemm<64, true><<<dim3(8, 1, BH), 256, SMEM64>>>(
            P3, v3, nullptr, nullptr, nullptr, att3, 3 * T, HS, 3 * E, 3 * T, 3, 0);

        wsplit_kernel<<<E * E / 256, 256>>>(wp_l, w3, E, E, 0);
        hgemm<128, false><<<dim3(16, 6, 1), 256, SMEM128>>>(
            att3, w3, bproj + l * E, x, x, nullptr, 3 * E, E, E, 3 * E, 0, 0);

        layernorm_kernel<<<ROWS, 256>>>(x, ln2_g + l * E, ln2_b + l * E, xn3);
        wsplit_kernel<<<E * F4 / 256, 256>>>(wfc_l, w3, F4, F4, 0);
        hgemm<128, true><<<dim3(16, 24, 1), 256, SMEM128>>>(
            xn3, w3, bfc + (size_t)l * F4, nullptr, nullptr, h3, 3 * E, F4, 3 * F4, 3 * E, 0, 1);
        wsplit_kernel<<<F4 * E / 256, 256>>>(wp2_l, w3, E, E, 0);
        hgemm<128, false><<<dim3(16, 6, 1), 256, SMEM128>>>(
            h3, w3, bpr2 + l * E, x, x, nullptr, 3 * F4, E, E, 3 * F4, 0, 0);
    }

    layernorm_kernel<<<ROWS, 256>>>(x, lnf_g, lnf_b, xn3);
    wsplit_kernel<<<E * VOCAB / 256, 256>>>(lm_w, lm3, VOCAB, VOCAB, 0);
    hgemm<128, false><<<dim3(16, VOCAB / 128, 1), 256, SMEM128>>>(
        xn3, lm3, lm_b, nullptr, out, nullptr, 3 * E, VOCAB, VOCAB, 3 * E, 0, 0);
}